// round 2
// baseline (speedup 1.0000x reference)
#include <cuda_runtime.h>
#include <cstdint>

// ---------------- problem constants ----------------
#define Nn   100000
#define Ee   600000
#define Gg   64
#define FIN  32
#define Wd   128
#define EPSv 1e-5f

// ---------------- device scratch (static, no allocs) ----------------
__device__ float g_h[(size_t)Nn * Wd];     // 51.2 MB
__device__ float g_a[(size_t)Nn * Wd];     // 51.2 MB
__device__ float g_dinv[Nn];
__device__ int   g_deg[Nn];
__device__ float g_stats[2 * Wd];          // sums -> (scale, shift) after finalize
__device__ float g_pool[Gg * Wd];

// ---------------- zero kernels (keep everything capturable) ----------------
__global__ void k_zero_misc() {
    int i = blockIdx.x * blockDim.x + threadIdx.x;
    if (i < Nn) g_deg[i] = 0;
    if (i < 2 * Wd) g_stats[i] = 0.f;
    if (i < Gg * Wd) g_pool[i] = 0.f;
}

__global__ void k_zero_a() {
    size_t i = (size_t)blockIdx.x * blockDim.x + threadIdx.x;
    if (i < (size_t)Nn * Wd / 4) {
        float4 z = make_float4(0.f, 0.f, 0.f, 0.f);
        ((float4*)g_a)[i] = z;
    }
}

// ---------------- degree / normalization ----------------
__global__ void k_deg(const int* __restrict__ dst) {
    int e = blockIdx.x * blockDim.x + threadIdx.x;
    if (e < Ee) atomicAdd(&g_deg[dst[e]], 1);
}

__global__ void k_dinv() {
    int i = blockIdx.x * blockDim.x + threadIdx.x;
    if (i < Nn) g_dinv[i] = rsqrtf((float)g_deg[i] + 1.0f);
}

// ---------------- edge scatter: g_a[dst] += g_h[src] * dinv[src]*dinv[dst] ----------------
// one warp per edge, 4 features per lane, vector reduction (no-return atomic)
__global__ void k_scatter(const int* __restrict__ src, const int* __restrict__ dst) {
    int idx  = blockIdx.x * blockDim.x + threadIdx.x;
    int e    = idx >> 5;
    int lane = idx & 31;
    if (e >= Ee) return;
    int s = src[e], d = dst[e];
    float w = g_dinv[s] * g_dinv[d];
    float4 v = *(const float4*)&g_h[(size_t)s * Wd + lane * 4];
    float* ap = &g_a[(size_t)d * Wd + lane * 4];
    asm volatile("red.relaxed.gpu.global.add.v4.f32 [%0], {%1, %2, %3, %4};"
                 :: "l"(ap), "f"(v.x * w), "f"(v.y * w), "f"(v.z * w), "f"(v.w * w)
                 : "memory");
}

// ---------------- combine: g_a = relu(g_a + g_h * dinv^2 + b) ----------------
__global__ void k_combine(const float* __restrict__ b) {
    size_t idx = (size_t)blockIdx.x * blockDim.x + threadIdx.x;   // float4 index
    if (idx >= (size_t)Nn * Wd / 4) return;
    int c4 = (int)(idx & 31);
    int i  = (int)(idx >> 5);
    float dv = g_dinv[i];
    float ds = dv * dv;
    float4 a = ((float4*)g_a)[idx];
    float4 h = ((const float4*)g_h)[idx];
    float4 bb = ((const float4*)b)[c4];
    a.x = fmaxf(fmaf(h.x, ds, a.x) + bb.x, 0.f);
    a.y = fmaxf(fmaf(h.y, ds, a.y) + bb.y, 0.f);
    a.z = fmaxf(fmaf(h.z, ds, a.z) + bb.z, 0.f);
    a.w = fmaxf(fmaf(h.w, ds, a.w) + bb.w, 0.f);
    ((float4*)g_a)[idx] = a;
}

// ---------------- SGEMM: C[N,128] = op(A)[N,K] @ B[K,128] ----------------
// 128x128 block tile, 256 threads, 8x8 micro-tile, BK=16.
// BNA: apply per-column (feature) affine+relu to A on load (uses g_stats).
template <bool BNA, bool BIAS, bool RELU>
__global__ __launch_bounds__(256) void k_gemm(const float* __restrict__ A,
                                              const float* __restrict__ Bm,
                                              const float* __restrict__ bias,
                                              float* __restrict__ C, int K) {
    __shared__ float As[16][132];   // transposed, padded
    __shared__ float Bs[16][128];
    int tid = threadIdx.x;
    int rb  = blockIdx.x * 128;
    int tx  = tid & 15;             // col group (8 cols)
    int ty  = tid >> 4;             // row group (8 rows)
    int lr  = tid >> 2;             // A-load local row 0..63
    int kq  = (tid & 3) * 4;        // A-load k-quad
    int bk  = tid >> 4;             // B-load k 0..15
    int bc  = (tid & 15) * 8;       // B-load col

    float acc[8][8];
#pragma unroll
    for (int i = 0; i < 8; i++)
#pragma unroll
        for (int j = 0; j < 8; j++) acc[i][j] = 0.f;

    for (int kc = 0; kc < K; kc += 16) {
        // --- load A tile (rows lr, lr+64) ---
#pragma unroll
        for (int h = 0; h < 2; h++) {
            int r = rb + lr + h * 64;
            float4 v = make_float4(0.f, 0.f, 0.f, 0.f);
            if (r < Nn) v = *(const float4*)&A[(size_t)r * K + kc + kq];
            if (BNA) {
                int c0 = kc + kq;
                v.x = fmaxf(fmaf(v.x, g_stats[c0 + 0], g_stats[Wd + c0 + 0]), 0.f);
                v.y = fmaxf(fmaf(v.y, g_stats[c0 + 1], g_stats[Wd + c0 + 1]), 0.f);
                v.z = fmaxf(fmaf(v.z, g_stats[c0 + 2], g_stats[Wd + c0 + 2]), 0.f);
                v.w = fmaxf(fmaf(v.w, g_stats[c0 + 3], g_stats[Wd + c0 + 3]), 0.f);
            }
            As[kq + 0][lr + h * 64] = v.x;
            As[kq + 1][lr + h * 64] = v.y;
            As[kq + 2][lr + h * 64] = v.z;
            As[kq + 3][lr + h * 64] = v.w;
        }
        // --- load B tile ---
        {
            const float* bp = &Bm[(size_t)(kc + bk) * Wd + bc];
            float4 u0 = *(const float4*)(bp);
            float4 u1 = *(const float4*)(bp + 4);
            *(float4*)&Bs[bk][bc]     = u0;
            *(float4*)&Bs[bk][bc + 4] = u1;
        }
        __syncthreads();

#pragma unroll
        for (int k = 0; k < 16; k++) {
            float4 a0 = *(const float4*)&As[k][ty * 8];
            float4 a1 = *(const float4*)&As[k][ty * 8 + 4];
            float4 b0 = *(const float4*)&Bs[k][tx * 8];
            float4 b1 = *(const float4*)&Bs[k][tx * 8 + 4];
            float av[8] = {a0.x, a0.y, a0.z, a0.w, a1.x, a1.y, a1.z, a1.w};
            float bv[8] = {b0.x, b0.y, b0.z, b0.w, b1.x, b1.y, b1.z, b1.w};
#pragma unroll
            for (int i = 0; i < 8; i++)
#pragma unroll
                for (int j = 0; j < 8; j++) acc[i][j] = fmaf(av[i], bv[j], acc[i][j]);
        }
        __syncthreads();
    }

    // --- epilogue ---
#pragma unroll
    for (int i = 0; i < 8; i++) {
        int r = rb + ty * 8 + i;
        if (r < Nn) {
            float out[8];
#pragma unroll
            for (int j = 0; j < 8; j++) {
                float v = acc[i][j];
                if (BIAS) v += bias[tx * 8 + j];
                if (RELU) v = fmaxf(v, 0.f);
                out[j] = v;
            }
            float* cp = &C[(size_t)r * Wd + tx * 8];
            *(float4*)(cp)     = make_float4(out[0], out[1], out[2], out[3]);
            *(float4*)(cp + 4) = make_float4(out[4], out[5], out[6], out[7]);
        }
    }
}

// ---------------- BN stats over g_h (128 cols, N rows) ----------------
__global__ void k_bnstats() {
    int c = threadIdx.x;   // 128 threads
    float s = 0.f, q = 0.f;
    for (int r = blockIdx.x; r < Nn; r += gridDim.x) {
        float v = g_h[(size_t)r * Wd + c];
        s += v;
        q += v * v;
    }
    atomicAdd(&g_stats[c], s);
    atomicAdd(&g_stats[Wd + c], q);
}

__global__ void k_bnfin(const float* __restrict__ gamma, const float* __restrict__ beta) {
    int c = threadIdx.x;  // 128
    float mu  = g_stats[c] * (1.f / Nn);
    float var = g_stats[Wd + c] * (1.f / Nn) - mu * mu;
    float rs  = rsqrtf(var + EPSv);
    float sc  = gamma[c] * rs;
    g_stats[c]      = sc;                // scale
    g_stats[Wd + c] = beta[c] - mu * sc; // shift
}

// ---------------- per-graph max pool (batch is sorted) ----------------
#define POOL_ROWS 500
__global__ void k_segmax(const int* __restrict__ batch) {
    int c  = threadIdx.x;              // 128 threads, one feature each
    int r0 = blockIdx.x * POOL_ROWS;
    int r1 = r0 + POOL_ROWS;           // Nn % POOL_ROWS == 0
    int cur = batch[r0];
    float m = g_a[(size_t)r0 * Wd + c];
    for (int r = r0 + 1; r < r1; r++) {
        int gID = batch[r];
        float v = g_a[(size_t)r * Wd + c];
        if (gID != cur) {
            atomicMax((int*)&g_pool[cur * Wd + c], __float_as_int(m));
            cur = gID;
            m = v;
        } else {
            m = fmaxf(m, v);
        }
    }
    atomicMax((int*)&g_pool[cur * Wd + c], __float_as_int(m));
}

// ---------------- head MLP on [64,128] pooled features ----------------
__global__ void k_final(const float* __restrict__ W5, const float* __restrict__ b5,
                        const float* __restrict__ g2, const float* __restrict__ be2,
                        const float* __restrict__ W6, const float* __restrict__ b6,
                        float* __restrict__ out) {
    __shared__ float S[64][65];
    __shared__ float sc[64], tc[64];
    int tid = threadIdx.x;  // 256
    for (int idx = tid; idx < 64 * 64; idx += 256) {
        int r = idx >> 6, c = idx & 63;
        float acc = b5[c];
        for (int k = 0; k < 128; k++) acc = fmaf(g_pool[r * 128 + k], W5[k * 64 + c], acc);
        S[r][c] = acc;
    }
    __syncthreads();
    if (tid < 64) {
        int c = tid;
        float s = 0.f, q = 0.f;
        for (int r = 0; r < 64; r++) { float v = S[r][c]; s += v; q += v * v; }
        float mu  = s * (1.f / 64);
        float var = q * (1.f / 64) - mu * mu;
        float rs  = rsqrtf(var + EPSv);
        float s_  = g2[c] * rs;
        sc[c] = s_;
        tc[c] = be2[c] - mu * s_;
    }
    __syncthreads();
    if (tid < 64) {
        int r = tid;
        float o = b6[0];
        for (int c = 0; c < 64; c++) {
            float v = fmaxf(fmaf(S[r][c], sc[c], tc[c]), 0.f);
            o = fmaf(v, W6[c], o);
        }
        out[r] = o;
    }
}

// ---------------- launch ----------------
extern "C" void kernel_launch(void* const* d_in, const int* in_sizes, int n_in,
                              void* d_out, int out_size) {
    const float* x    = (const float*)d_in[0];
    const int*   ei   = (const int*)d_in[1];
    const int*   src  = ei;
    const int*   dst  = ei + Ee;
    const int*   batch= (const int*)d_in[2];
    const float* W1 = (const float*)d_in[3];
    const float* b1 = (const float*)d_in[4];
    const float* W2 = (const float*)d_in[5];
    const float* b2 = (const float*)d_in[6];
    const float* W3 = (const float*)d_in[7];
    const float* b3 = (const float*)d_in[8];
    const float* g1 = (const float*)d_in[9];
    const float* be1= (const float*)d_in[10];
    const float* W4 = (const float*)d_in[11];
    const float* b4 = (const float*)d_in[12];
    const float* W5 = (const float*)d_in[13];
    const float* b5 = (const float*)d_in[14];
    const float* g2 = (const float*)d_in[15];
    const float* be2= (const float*)d_in[16];
    const float* W6 = (const float*)d_in[17];
    const float* b6 = (const float*)d_in[18];
    float* out = (float*)d_out;

    // CRITICAL: resolve true device addresses of the __device__ scratch arrays.
    // (Passing the symbol directly from host code passes the host shadow address.)
    float *h_ptr = nullptr, *a_ptr = nullptr;
    cudaGetSymbolAddress((void**)&h_ptr, g_h);
    cudaGetSymbolAddress((void**)&a_ptr, g_a);

    const int TB = 256;
    int gridN    = (Nn + TB - 1) / TB;
    int gridE    = (Ee + TB - 1) / TB;
    int gridA4   = (Nn * (Wd / 4) + TB - 1) / TB;       // float4 elements of g_a
    int gridScat = ((Ee * 32) + TB - 1) / TB;
    int gridGemm = (Nn + 127) / 128;

    k_zero_misc<<<gridN, TB>>>();
    k_deg<<<gridE, TB>>>(dst);
    k_dinv<<<gridN, TB>>>();

    // conv1: h = x @ W1 ; agg ; relu(agg + h*dinv^2 + b1)
    k_gemm<false, false, false><<<gridGemm, TB>>>(x, W1, b1, h_ptr, FIN);
    k_zero_a<<<gridA4, TB>>>();
    k_scatter<<<gridScat, TB>>>(src, dst);
    k_combine<<<gridA4, TB>>>(b1);

    // conv2
    k_gemm<false, false, false><<<gridGemm, TB>>>(a_ptr, W2, b2, h_ptr, Wd);
    k_zero_a<<<gridA4, TB>>>();
    k_scatter<<<gridScat, TB>>>(src, dst);
    k_combine<<<gridA4, TB>>>(b2);

    // mlp_first: t = h2 @ W3 + b3 ; BN stats ; z = relu(relu(bn(t)) @ W4 + b4)
    k_gemm<false, true, false><<<gridGemm, TB>>>(a_ptr, W3, b3, h_ptr, Wd);
    k_bnstats<<<256, 128>>>();
    k_bnfin<<<1, 128>>>(g1, be1);
    k_gemm<true, true, true><<<gridGemm, TB>>>(h_ptr, W4, b4, a_ptr, Wd);

    // global max pool + head
    k_segmax<<<Nn / POOL_ROWS, 128>>>(batch);
    k_final<<<1, 256>>>(W5, b5, g2, be2, W6, b6, out);
}

// round 4
// speedup vs baseline: 1.1538x; 1.1538x over previous
#include <cuda_runtime.h>
#include <cstdint>

// ---------------- problem constants ----------------
#define Nn   100000
#define Ee   600000
#define Gg   64
#define FIN  32
#define Wd   128
#define EPSv 1e-5f

// ---------------- device scratch (static, no allocs) ----------------
__device__ float g_h[(size_t)Nn * Wd];     // 51.2 MB  raw h = A@W (no bias)
__device__ float g_a[(size_t)Nn * Wd];     // 51.2 MB  accumulation buffer (self-init + scatter)
__device__ float g_dinv[Nn];
__device__ int   g_deg[Nn];
__device__ float g_stats[2 * Wd];          // sums -> (scale, shift) after finalize
__device__ float g_pool[Gg * Wd];

// ---------------- zero / degree / normalization ----------------
__global__ void k_zero_misc() {
    int i = blockIdx.x * blockDim.x + threadIdx.x;
    if (i < Nn) g_deg[i] = 0;
    if (i < 2 * Wd) g_stats[i] = 0.f;
    if (i < Gg * Wd) g_pool[i] = 0.f;
}

__global__ void k_deg(const int* __restrict__ dst) {
    int e = blockIdx.x * blockDim.x + threadIdx.x;
    if (e < Ee) atomicAdd(&g_deg[dst[e]], 1);
}

__global__ void k_dinv() {
    int i = blockIdx.x * blockDim.x + threadIdx.x;
    if (i < Nn) g_dinv[i] = rsqrtf((float)g_deg[i] + 1.0f);
}

// ---------------- edge scatter: g_a[dst] += g_h[src] * dinv[src]*dinv[dst] ----------------
__global__ void k_scatter(const int* __restrict__ src, const int* __restrict__ dst) {
    int idx  = blockIdx.x * blockDim.x + threadIdx.x;
    int e    = idx >> 5;
    int lane = idx & 31;
    if (e >= Ee) return;
    int s = src[e], d = dst[e];
    float w = g_dinv[s] * g_dinv[d];
    float4 v = *(const float4*)&g_h[(size_t)s * Wd + lane * 4];
    float* ap = &g_a[(size_t)d * Wd + lane * 4];
    asm volatile("red.relaxed.gpu.global.add.v4.f32 [%0], {%1, %2, %3, %4};"
                 :: "l"(ap), "f"(v.x * w), "f"(v.y * w), "f"(v.z * w), "f"(v.w * w)
                 : "memory");
}

// ---------------- fused SGEMM ----------------
// C[N,128] = f(A)[N,K] @ B[K,128], 128x128 tile, 256 threads, 8x8 microtile,
// packed fma.rn.f32x2 inner loop, double-buffered smem, reg prefetch.
enum { LOAD_NONE = 0, LOAD_RELU = 1, LOAD_BN = 2 };

template <int LOADM, bool BIAS, bool RELU, bool SELF, bool STATS>
__global__ __launch_bounds__(256, 2) void k_gemm(const float* __restrict__ A,
                                                 const float* __restrict__ Bm,
                                                 const float* __restrict__ bias,
                                                 float* __restrict__ C, int K) {
    __shared__ float As[2][16][132];
    __shared__ float Bs[2][16][128];
    __shared__ float s_st[2][128];

    int tid = threadIdx.x;
    int rb  = blockIdx.x * 128;
    int tx  = tid & 15;
    int ty  = tid >> 4;
    int lr  = tid >> 2;
    int kq  = (tid & 3) * 4;
    int bk  = tid >> 4;
    int bc  = (tid & 15) * 8;

    float4 pa[2], pb[2];

    auto ldTile = [&](int kc) {
#pragma unroll
        for (int h = 0; h < 2; h++) {
            int r = rb + lr + h * 64;
            float4 v = make_float4(0.f, 0.f, 0.f, 0.f);
            if (r < Nn) v = *(const float4*)&A[(size_t)r * K + kc * 16 + kq];
            pa[h] = v;
        }
        const float* bp = &Bm[(size_t)(kc * 16 + bk) * Wd + bc];
        pb[0] = *(const float4*)bp;
        pb[1] = *(const float4*)(bp + 4);
    };

    auto stTile = [&](int buf, int kc) {
#pragma unroll
        for (int h = 0; h < 2; h++) {
            float4 v = pa[h];
            if (LOADM == LOAD_RELU) {
                v.x = fmaxf(v.x, 0.f); v.y = fmaxf(v.y, 0.f);
                v.z = fmaxf(v.z, 0.f); v.w = fmaxf(v.w, 0.f);
            } else if (LOADM == LOAD_BN) {
                int c0 = kc * 16 + kq;
                v.x = fmaxf(fmaf(v.x, g_stats[c0 + 0], g_stats[Wd + c0 + 0]), 0.f);
                v.y = fmaxf(fmaf(v.y, g_stats[c0 + 1], g_stats[Wd + c0 + 1]), 0.f);
                v.z = fmaxf(fmaf(v.z, g_stats[c0 + 2], g_stats[Wd + c0 + 2]), 0.f);
                v.w = fmaxf(fmaf(v.w, g_stats[c0 + 3], g_stats[Wd + c0 + 3]), 0.f);
            }
            As[buf][kq + 0][lr + h * 64] = v.x;
            As[buf][kq + 1][lr + h * 64] = v.y;
            As[buf][kq + 2][lr + h * 64] = v.z;
            As[buf][kq + 3][lr + h * 64] = v.w;
        }
        *(float4*)&Bs[buf][bk][bc]     = pb[0];
        *(float4*)&Bs[buf][bk][bc + 4] = pb[1];
    };

    unsigned long long acc[8][4];
#pragma unroll
    for (int i = 0; i < 8; i++)
#pragma unroll
        for (int j = 0; j < 4; j++) acc[i][j] = 0ull;

    int nk = K >> 4;
    ldTile(0);
    stTile(0, 0);
    __syncthreads();

    for (int kc = 0; kc < nk; kc++) {
        if (kc + 1 < nk) ldTile(kc + 1);
        int buf = kc & 1;
#pragma unroll
        for (int k = 0; k < 16; k++) {
            float4 a0 = *(const float4*)&As[buf][k][ty * 8];
            float4 a1 = *(const float4*)&As[buf][k][ty * 8 + 4];
            // b fragment: columns tx*8 .. tx*8+7 (each ulonglong2 = 4 floats)
            ulonglong2 b0 = *(const ulonglong2*)&Bs[buf][k][tx * 8];
            ulonglong2 b1 = *(const ulonglong2*)&Bs[buf][k][tx * 8 + 4];
            unsigned long long bb[4] = {b0.x, b0.y, b1.x, b1.y};
            float av[8] = {a0.x, a0.y, a0.z, a0.w, a1.x, a1.y, a1.z, a1.w};
#pragma unroll
            for (int i = 0; i < 8; i++) {
                unsigned long long ad;
                unsigned int ai = __float_as_uint(av[i]);
                asm("mov.b64 %0, {%1, %1};" : "=l"(ad) : "r"(ai));
#pragma unroll
                for (int j = 0; j < 4; j++)
                    asm("fma.rn.f32x2 %0, %1, %2, %0;"
                        : "+l"(acc[i][j]) : "l"(ad), "l"(bb[j]));
            }
        }
        if (kc + 1 < nk) {
            stTile((kc + 1) & 1, kc + 1);
            __syncthreads();
        }
    }

    // ---------------- epilogue ----------------
    if (STATS) {
        s_st[tid >> 7][tid & 127] = 0.f;
        __syncthreads();
    }

    float cs[8], cq[8];
    if (STATS) {
#pragma unroll
        for (int j = 0; j < 8; j++) { cs[j] = 0.f; cq[j] = 0.f; }
    }

#pragma unroll
    for (int i = 0; i < 8; i++) {
        int r = rb + ty * 8 + i;
        if (r < Nn) {
            float out[8];
#pragma unroll
            for (int j = 0; j < 4; j++) {
                union { unsigned long long u; float2 f; } t;
                t.u = acc[i][j];
                out[2 * j]     = t.f.x;
                out[2 * j + 1] = t.f.y;
            }
            float os[8];
#pragma unroll
            for (int j = 0; j < 8; j++) {
                float v = out[j];
                if (BIAS) v += bias[tx * 8 + j];
                if (RELU) v = fmaxf(v, 0.f);
                os[j] = v;
                if (STATS) { cs[j] += v; cq[j] += v * v; }
            }
            float* cp = &C[(size_t)r * Wd + tx * 8];
            *(float4*)(cp)     = make_float4(os[0], os[1], os[2], os[3]);
            *(float4*)(cp + 4) = make_float4(os[4], os[5], os[6], os[7]);
            if (SELF) {
                float dv = g_dinv[r];
                float ds = dv * dv;
                float* ap = &g_a[(size_t)r * Wd + tx * 8];
                float4 s0, s1;
                s0.x = fmaf(out[0], ds, bias[tx * 8 + 0]);
                s0.y = fmaf(out[1], ds, bias[tx * 8 + 1]);
                s0.z = fmaf(out[2], ds, bias[tx * 8 + 2]);
                s0.w = fmaf(out[3], ds, bias[tx * 8 + 3]);
                s1.x = fmaf(out[4], ds, bias[tx * 8 + 4]);
                s1.y = fmaf(out[5], ds, bias[tx * 8 + 5]);
                s1.z = fmaf(out[6], ds, bias[tx * 8 + 6]);
                s1.w = fmaf(out[7], ds, bias[tx * 8 + 7]);
                *(float4*)(ap)     = s0;
                *(float4*)(ap + 4) = s1;
            }
        }
    }

    if (STATS) {
#pragma unroll
        for (int j = 0; j < 8; j++) {
            atomicAdd(&s_st[0][tx * 8 + j], cs[j]);
            atomicAdd(&s_st[1][tx * 8 + j], cq[j]);
        }
        __syncthreads();
        if (tid < 128) {
            atomicAdd(&g_stats[tid],      s_st[0][tid]);
            atomicAdd(&g_stats[Wd + tid], s_st[1][tid]);
        }
    }
}

// ---------------- BN finalize ----------------
__global__ void k_bnfin(const float* __restrict__ gamma, const float* __restrict__ beta) {
    int c = threadIdx.x;  // 128
    float mu  = g_stats[c] * (1.f / Nn);
    float var = g_stats[Wd + c] * (1.f / Nn) - mu * mu;
    float rs  = rsqrtf(var + EPSv);
    float sc  = gamma[c] * rs;
    g_stats[c]      = sc;                // scale
    g_stats[Wd + c] = beta[c] - mu * sc; // shift
}

// ---------------- per-graph max pool (batch is sorted) ----------------
#define POOL_ROWS 500
__global__ void k_segmax(const int* __restrict__ batch) {
    int c  = threadIdx.x;              // 128 threads, one feature each
    int r0 = blockIdx.x * POOL_ROWS;
    int r1 = r0 + POOL_ROWS;
    int cur = batch[r0];
    float m = g_a[(size_t)r0 * Wd + c];
    for (int r = r0 + 1; r < r1; r++) {
        int gID = batch[r];
        float v = g_a[(size_t)r * Wd + c];
        if (gID != cur) {
            atomicMax((int*)&g_pool[cur * Wd + c], __float_as_int(m));
            cur = gID;
            m = v;
        } else {
            m = fmaxf(m, v);
        }
    }
    atomicMax((int*)&g_pool[cur * Wd + c], __float_as_int(m));
}

// ---------------- head MLP on [64,128] pooled features ----------------
__global__ void k_final(const float* __restrict__ W5, const float* __restrict__ b5,
                        const float* __restrict__ g2, const float* __restrict__ be2,
                        const float* __restrict__ W6, const float* __restrict__ b6,
                        float* __restrict__ out) {
    __shared__ float S[64][65];
    __shared__ float sc[64], tc[64];
    int tid = threadIdx.x;  // 256
    for (int idx = tid; idx < 64 * 64; idx += 256) {
        int r = idx >> 6, c = idx & 63;
        float acc = b5[c];
        for (int k = 0; k < 128; k++) acc = fmaf(g_pool[r * 128 + k], W5[k * 64 + c], acc);
        S[r][c] = acc;
    }
    __syncthreads();
    if (tid < 64) {
        int c = tid;
        float s = 0.f, q = 0.f;
        for (int r = 0; r < 64; r++) { float v = S[r][c]; s += v; q += v * v; }
        float mu  = s * (1.f / 64);
        float var = q * (1.f / 64) - mu * mu;
        float rs  = rsqrtf(var + EPSv);
        float s_  = g2[c] * rs;
        sc[c] = s_;
        tc[c] = be2[c] - mu * s_;
    }
    __syncthreads();
    if (tid < 64) {
        int r = tid;
        float o = b6[0];
        for (int c = 0; c < 64; c++) {
            float v = fmaxf(fmaf(S[r][c], sc[c], tc[c]), 0.f);
            o = fmaf(v, W6[c], o);
        }
        out[r] = o;
    }
}

// ---------------- launch ----------------
extern "C" void kernel_launch(void* const* d_in, const int* in_sizes, int n_in,
                              void* d_out, int out_size) {
    const float* x    = (const float*)d_in[0];
    const int*   ei   = (const int*)d_in[1];
    const int*   src  = ei;
    const int*   dst  = ei + Ee;
    const int*   batch= (const int*)d_in[2];
    const float* W1 = (const float*)d_in[3];
    const float* b1 = (const float*)d_in[4];
    const float* W2 = (const float*)d_in[5];
    const float* b2 = (const float*)d_in[6];
    const float* W3 = (const float*)d_in[7];
    const float* b3 = (const float*)d_in[8];
    const float* g1 = (const float*)d_in[9];
    const float* be1= (const float*)d_in[10];
    const float* W4 = (const float*)d_in[11];
    const float* b4 = (const float*)d_in[12];
    const float* W5 = (const float*)d_in[13];
    const float* b5 = (const float*)d_in[14];
    const float* g2 = (const float*)d_in[15];
    const float* be2= (const float*)d_in[16];
    const float* W6 = (const float*)d_in[17];
    const float* b6 = (const float*)d_in[18];
    float* out = (float*)d_out;

    // resolve true device addresses of __device__ scratch
    float *h_ptr = nullptr, *a_ptr = nullptr;
    cudaGetSymbolAddress((void**)&h_ptr, g_h);
    cudaGetSymbolAddress((void**)&a_ptr, g_a);

    const int TB = 256;
    int gridN    = (Nn + TB - 1) / TB;
    int gridE    = (Ee + TB - 1) / TB;
    int gridScat = ((Ee * 32) + TB - 1) / TB;
    int gridGemm = (Nn + 127) / 128;

    k_zero_misc<<<gridN, TB>>>();
    k_deg<<<gridE, TB>>>(dst);
    k_dinv<<<gridN, TB>>>();

    // conv1: g_h = x@W1 ; g_a = g_h*dinv^2 + b1 (epilogue) ; scatter adds edges
    k_gemm<LOAD_NONE, false, false, true, false><<<gridGemm, TB>>>(x, W1, b1, h_ptr, FIN);
    k_scatter<<<gridScat, TB>>>(src, dst);

    // conv2: A = relu(g_a) on load
    k_gemm<LOAD_RELU, false, false, true, false><<<gridGemm, TB>>>(a_ptr, W2, b2, h_ptr, Wd);
    k_scatter<<<gridScat, TB>>>(src, dst);

    // mlp_first: g_h = relu(g_a)@W3 + b3, with fused BN stats
    k_gemm<LOAD_RELU, true, false, false, true><<<gridGemm, TB>>>(a_ptr, W3, b3, h_ptr, Wd);
    k_bnfin<<<1, 128>>>(g1, be1);
    // g_a = relu( relu(bn(g_h)) @ W4 + b4 )
    k_gemm<LOAD_BN, true, true, false, false><<<gridGemm, TB>>>(h_ptr, W4, b4, a_ptr, Wd);

    // global max pool + head
    k_segmax<<<Nn / POOL_ROWS, 128>>>(batch);
    k_final<<<1, 256>>>(W5, b5, g2, be2, W6, b6, out);
}